// round 12
// baseline (speedup 1.0000x reference)
#include <cuda_runtime.h>
#include <math.h>

#define TPB 128

__device__ __forceinline__ float2 cmul(float2 a, float2 b) {
    float2 r;
    r.x = fmaf(-a.y, b.y, a.x * b.x);
    r.y = fmaf( a.x, b.y, a.y * b.x);
    return r;
}

// per-state smem table (float2):
// P4[0..31]  = A_bar^(4r)
// W[0..3]    = A_bar^(128q)
// S          = A_bar^512
// Rot[0..2]  = (cos, -sin) of A_bar^{1,2,3}
// PQ         = (2 Re S, -|S|^2)
// CF         = 2 * C * B_bar
struct STab {
    float2 P4[32];
    float2 W[4];
    float2 S;
    float2 Rot[3];
    float2 PQ;
    float2 CF;
};

__global__ __launch_bounds__(TPB, 12) void pmsn_kernel(
    const float* __restrict__ log_dt,
    const float* __restrict__ log_A_real,
    const float* __restrict__ A_imag,
    const float* __restrict__ VinvB_real,
    const float* __restrict__ VinvB_imag,
    const float* __restrict__ CV_real,
    const float* __restrict__ CV_imag,
    float* __restrict__ out, int L)
{
    __shared__ STab Tsm[2];
    const int h = blockIdx.x;
    const int t = threadIdx.x;

    // ---- prologue: 2 lanes, one paired-state each; streamed to smem, low regs ----
    if (t < 2) {
        const int s = t;
        // s-th state with A_imag > 0 (conjugate-pair representative; validated R9-R11)
        int n = 3, cnt = 0;
#pragma unroll
        for (int k = 0; k < 4; ++k) {
            const float a = A_imag[h * 4 + k];
            if (a > 0.0f) { if (cnt == s) n = k; ++cnt; }
        }
        const int idx = h * 4 + n;

        const float dt  = expf(log_dt[h]);
        const float Are = -expf(log_A_real[idx]);
        const float Aim = A_imag[idx];
        const float adr = Are * dt;
        const float adi = Aim * dt;              // |adi| < ~2 rad

        float sn, cs;
        sincosf(adi, &sn, &cs);
        const float m = expf(adr);
        const float2 A1 = make_float2(m * cs, m * sn);
        const float2 A2 = cmul(A1, A1);
        const float2 A3 = cmul(A2, A1);
        const float2 A4 = cmul(A2, A2);

        STab* T = &Tsm[s];
        float2 run = make_float2(1.0f, 0.0f);
#pragma unroll
        for (int r = 0; r < 32; ++r) {           // P4[r] = A4^r
            T->P4[r] = run;
            run = cmul(run, A4);
        }
        // run = A4^32 = A_bar^128
        const float2 A128 = run;
        const float2 A256 = cmul(A128, A128);
        T->W[0] = make_float2(1.0f, 0.0f);
        T->W[1] = A128;
        T->W[2] = A256;
        T->W[3] = cmul(A256, A128);
        const float2 S = cmul(A256, A256);       // A_bar^512
        T->S = S;
        T->Rot[0] = make_float2(A1.x, -A1.y);
        T->Rot[1] = make_float2(A2.x, -A2.y);
        T->Rot[2] = make_float2(A3.x, -A3.y);
        T->PQ = make_float2(S.x + S.x, -fmaf(S.x, S.x, S.y * S.y));

        // coef = 2 * C * (A_bar - 1)/A * B
        const float inv = 1.0f / fmaf(Are, Are, Aim * Aim);
        const float iAr =  Are * inv, iAi = -Aim * inv;
        const float mr = A1.x - 1.0f, mi = A1.y;
        const float qr = mr * iAr - mi * iAi;
        const float qi = mr * iAi + mi * iAr;
        const float Br = VinvB_real[idx], Bi = VinvB_imag[idx];
        const float bbr = qr * Br - qi * Bi;
        const float bbi = qr * Bi + qi * Br;
        const float Cr = CV_real[idx], Ci = CV_imag[idx];
        T->CF = make_float2(2.0f * (Cr * bbr - Ci * bbi),
                            2.0f * (Cr * bbi + Ci * bbr));
    }
    __syncthreads();

    // ---- main: l = 4t + i + 512j ----
    const int q = t >> 5;
    const int r = t & 31;

    float xc[2][4], xp[2][4], pn[2], qn[2];
#pragma unroll
    for (int s = 0; s < 2; ++s) {
        const STab* __restrict__ T = &Tsm[s];
        const float2 w  = cmul(T->W[q], T->P4[r]);   // A_bar^(4t)
        const float2 v  = cmul(w, T->CF);            // j=0 state
        const float2 u2 = cmul(v, T->S);             // j=1 state
        xp[s][0] = v.x;
        xc[s][0] = u2.x;
#pragma unroll
        for (int i = 0; i < 3; ++i) {
            const float2 ro = T->Rot[i];             // (cos, -sin)
            xp[s][i + 1] = fmaf(v.y,  ro.y, v.x  * ro.x);
            xc[s][i + 1] = fmaf(u2.y, ro.y, u2.x * ro.x);
        }
        pn[s] = T->PQ.x;
        qn[s] = T->PQ.y;
    }

    float* __restrict__ orow = out + (size_t)h * (size_t)L + 4 * t;
    const int NJ = L >> 9;    // L / 512 = 8

    *(float4*)orow = make_float4(xp[0][0] + xp[1][0], xp[0][1] + xp[1][1],
                                 xp[0][2] + xp[1][2], xp[0][3] + xp[1][3]);
    if (NJ > 1)
        *(float4*)(orow + 512) = make_float4(xc[0][0] + xc[1][0], xc[0][1] + xc[1][1],
                                             xc[0][2] + xc[1][2], xc[0][3] + xc[1][3]);

#pragma unroll 6
    for (int j = 2; j < NJ; ++j) {
#pragma unroll
        for (int s = 0; s < 2; ++s) {
#pragma unroll
            for (int i = 0; i < 4; ++i) {
                const float xn = fmaf(pn[s], xc[s][i], qn[s] * xp[s][i]);
                xp[s][i] = xc[s][i];
                xc[s][i] = xn;
            }
        }
        *(float4*)(orow + (size_t)j * 512) =
            make_float4(xc[0][0] + xc[1][0], xc[0][1] + xc[1][1],
                        xc[0][2] + xc[1][2], xc[0][3] + xc[1][3]);
    }
}

extern "C" void kernel_launch(void* const* d_in, const int* in_sizes, int n_in,
                              void* d_out, int out_size) {
    const float* log_dt     = (const float*)d_in[0];
    const float* log_A_real = (const float*)d_in[1];
    const float* A_imag     = (const float*)d_in[2];
    const float* VinvB_real = (const float*)d_in[3];
    const float* VinvB_imag = (const float*)d_in[4];
    const float* CV_real    = (const float*)d_in[5];
    const float* CV_imag    = (const float*)d_in[6];
    const int H = in_sizes[0];               // 2048
    const int L = out_size / H;              // 4096
    pmsn_kernel<<<H, TPB>>>(log_dt, log_A_real, A_imag,
                            VinvB_real, VinvB_imag,
                            CV_real, CV_imag, (float*)d_out, L);
}